// round 12
// baseline (speedup 1.0000x reference)
#include <cuda_runtime.h>
#include <cuda_fp16.h>
#include <cstdint>

#define B_   8
#define T_   2048
#define N_   512
#define M_   (B_*T_)      // 16384
#define L_   32           // scan chunk length == GEMM1 warp-tile m
#define NCH_ (T_/L_)      // 64

#define WSCALE 64.0f
#define WINV   (1.0f/64.0f)

typedef unsigned long long ull;

// Scratch
__device__ __half  g_uh[M_*N_];               // u as fp16
__device__ __half2 g_xh[M_*N_];               // x as fp16 complex (re=low, im=high)
__device__ float2  g_end[B_*NCH_*N_];
__device__ float2  g_pw[32*512];              // lam^{31-r} * WINV per (r, channel)
// Pre-transposed/swizzled fp16 weight tiles (scaled by WSCALE):
__device__ uint4 g_W1[8][8][1024];            // GEMM1 B'' (Neff=1024, K=512)
__device__ uint4 g_W2[4][16][1024];           // GEMM2 B'  (N=512, Keff=1024)

// ---------------------------------------------------------------------------
__device__ __forceinline__ uint32_t s2u(const void* p){
    uint32_t a;
    asm("{ .reg .u64 t; cvta.to.shared.u64 t, %1; cvt.u32.u64 %0, t; }" : "=r"(a) : "l"(p));
    return a;
}
#define SWZ(o) ((uint32_t)(o) ^ ((((uint32_t)(o))>>3)&0x70u))

__device__ __forceinline__ uint32_t cvt2h(float x0, float x1){
    uint32_t r;
    asm("cvt.rn.f16x2.f32 %0, %1, %2;" : "=r"(r) : "f"(x1), "f"(x0));
    return r;
}
__device__ __forceinline__ uint4 ldsm4(uint32_t addr){
    uint4 r;
    asm volatile("ldmatrix.sync.aligned.m8n8.x4.shared.b16 {%0,%1,%2,%3}, [%4];"
        : "=r"(r.x), "=r"(r.y), "=r"(r.z), "=r"(r.w) : "r"(addr));
    return r;
}
__device__ __forceinline__ void mma16816(float* c, uint4 a, uint32_t b0, uint32_t b1){
    asm volatile("mma.sync.aligned.m16n8k16.row.col.f32.f16.f16.f32 "
        "{%0,%1,%2,%3}, {%4,%5,%6,%7}, {%8,%9}, {%0,%1,%2,%3};"
        : "+f"(c[0]), "+f"(c[1]), "+f"(c[2]), "+f"(c[3])
        : "r"(a.x), "r"(a.y), "r"(a.z), "r"(a.w), "r"(b0), "r"(b1));
}
__device__ __forceinline__ void cpasync16(uint32_t dst, const void* src){
    asm volatile("cp.async.cg.shared.global [%0], [%1], 16;" :: "r"(dst), "l"(src));
}

// ---------------------------------------------------------------------------
// Merged prepass: [0,128) W1, [128,256) W2, [256,4352) u->fp16, [4352,4416) pw
// ---------------------------------------------------------------------------
__global__ __launch_bounds__(256) void prep_all(const float* __restrict__ u,
                                                const float* __restrict__ Bre,
                                                const float* __restrict__ Bim,
                                                const float* __restrict__ Cre,
                                                const float* __restrict__ Cim,
                                                const float* __restrict__ gamma,
                                                const float* __restrict__ nu,
                                                const float* __restrict__ theta)
{
    __shared__ float s0[64*36];
    __shared__ float s1[64*36];
    __shared__ float gs[64];
    int bid = blockIdx.x, tid = threadIdx.x;

    if (bid >= 4352){
        int item = (bid - 4352) * 256 + tid;     // 16384 items
        int r = item >> 9, nc = item & 511;
        int q = 31 - r;
        float en = expf(nu[nc]);
        float mg = expf(-(float)q * en) * WINV;
        float ang = (float)q * theta[nc];
        g_pw[r*512 + nc] = make_float2(mg * cosf(ang), mg * sinf(ang));
        return;
    }
    if (bid >= 256){
        int i = (bid - 256) * 256 + tid;
        const float4* p = (const float4*)(u) + (size_t)i*2;
        float4 a = p[0], b = p[1];
        uint4 H;
        H.x = cvt2h(a.x, a.y);
        H.y = cvt2h(a.z, a.w);
        H.z = cvt2h(b.x, b.y);
        H.w = cvt2h(b.z, b.w);
        ((uint4*)g_uh)[i] = H;
        return;
    }

    if (bid < 128){
        int kb = bid >> 4, nt = bid & 15;
        int n0 = nt*32, k0 = kb*64;
        #pragma unroll
        for (int i = 0; i < 2; i++){
            int idx = tid + 256*i;
            int row = idx >> 3, c4 = (idx & 7) * 4;
            *(float4*)&s0[row*36 + c4] = *(const float4*)&Bre[(size_t)(k0+row)*N_ + n0 + c4];
            *(float4*)&s1[row*36 + c4] = *(const float4*)&Bim[(size_t)(k0+row)*N_ + n0 + c4];
        }
        if (tid < 64) gs[tid] = gamma[k0 + tid];
        __syncthreads();
        #pragma unroll
        for (int i = 0; i < 2; i++){
            int uid = tid + 256*i;
            int jloc = uid >> 3, cl = uid & 7;
            int j = n0*2 + jloc;
            int nloc = jloc >> 1, p = jloc & 1;
            const float* sp = p ? s1 : s0;
            float vs[8];
            #pragma unroll
            for (int e = 0; e < 8; e++){
                int kl = cl*8 + e;
                vs[e] = sp[kl*36 + nloc] * gs[kl] * WSCALE;
            }
            uint4 H;
            H.x = cvt2h(vs[0], vs[1]);
            H.y = cvt2h(vs[2], vs[3]);
            H.z = cvt2h(vs[4], vs[5]);
            H.w = cvt2h(vs[6], vs[7]);
            int jl = j & 127;
            g_W1[j>>7][kb][jl*8 + (cl ^ (jl & 7))] = H;
        }
    } else {
        int b2 = bid - 128;
        int kb = b2 >> 3, jt = b2 & 7;
        int j0 = jt*64, k0 = kb*32;
        #pragma unroll
        for (int i = 0; i < 2; i++){
            int idx = tid + 256*i;
            int row = idx >> 4, c4 = (idx & 15) * 4;
            *(float4*)&s0[row*68 + c4] = *(const float4*)&Cre[(size_t)(k0+row)*N_ + j0 + c4];
            *(float4*)&s1[row*68 + c4] = *(const float4*)&Cim[(size_t)(k0+row)*N_ + j0 + c4];
        }
        __syncthreads();
        #pragma unroll
        for (int i = 0; i < 2; i++){
            int uid = tid + 256*i;
            int jloc = uid >> 3, cl = uid & 7;
            int j = j0 + jloc;
            float vs[8];
            #pragma unroll
            for (int e = 0; e < 8; e++){
                int kel = cl*8 + e;
                int kl = kel >> 1;
                float v = (kel & 1) ? -s1[kl*68 + jloc] : s0[kl*68 + jloc];
                vs[e] = v * WSCALE;
            }
            uint4 H;
            H.x = cvt2h(vs[0], vs[1]);
            H.y = cvt2h(vs[2], vs[3]);
            H.z = cvt2h(vs[4], vs[5]);
            H.w = cvt2h(vs[6], vs[7]);
            int jl = j & 127;
            g_W2[j>>7][kb][jl*8 + (cl ^ (jl & 7))] = H;
        }
    }
}

// ---------------------------------------------------------------------------
// Register fragments (double-buffered)
// ---------------------------------------------------------------------------
struct Frag { uint4 a[2]; uint4 b[4]; };

__device__ __forceinline__ void ldfrag(Frag& f, uint32_t stbase,
                                       int kk, int wm, int wn, int lane,
                                       uint32_t AH, uint32_t BH)
{
    #pragma unroll
    for (int mt = 0; mt < 2; mt++){
        uint32_t off = SWZ((wm*32 + mt*16 + (lane&15))*128 + (kk*2 + (lane>>4))*16);
        f.a[mt] = ldsm4(stbase + AH + off);
    }
    #pragma unroll
    for (int bt = 0; bt < 4; bt++){
        uint32_t off = SWZ((wn*64 + bt*16 + (lane&7) + ((lane>>4)<<3))*128
                           + (kk*2 + ((lane>>3)&1))*16);
        f.b[bt] = ldsm4(stbase + BH + off);
    }
}
__device__ __forceinline__ void mmastep(float acc[2][8][4], const Frag& f){
    #pragma unroll
    for (int bt = 0; bt < 4; bt++){
        #pragma unroll
        for (int mt = 0; mt < 2; mt++){
            mma16816(acc[mt][2*bt],   f.a[mt], f.b[bt].x, f.b[bt].y);
            mma16816(acc[mt][2*bt+1], f.a[mt], f.b[bt].z, f.b[bt].w);
        }
    }
}

// ---------------------------------------------------------------------------
// HMMA GEMM: 128x128 tile, 8 warps (4x2), warp 32x64.
// 4-stage cp.async smem pipeline + double-buffered register fragments.
// 1 CTA/SM (131KB smem). MODE 1: g_xh = uh @ W1 (+fused chunk ends).
// MODE 2: y = flat(g_xh) @ W2 + D*u.
// ---------------------------------------------------------------------------
template<int MODE>
__global__ __launch_bounds__(256, 1) void gemm_tc(const float* __restrict__ Dv,
                                                  float* __restrict__ yout)
{
    constexpr int KIT  = (MODE == 1) ? 8 : 16;
    constexpr int ROWB = (MODE == 1) ? 1024 : 2048;
    constexpr uint32_t STG = 32768;
    constexpr uint32_t AH = 0, BH = 16384;

    extern __shared__ char sm[];
    const uint32_t sb = s2u(sm);

    const int tid  = threadIdx.x;
    const int lane = tid & 31, warp = tid >> 5;
    const int wm = warp >> 1, wn = warp & 1;
    const int nb = blockIdx.x;
    const int m0 = blockIdx.y * 128;

    const char* Abase = (MODE == 1) ? (const char*)g_uh : (const char*)g_xh;
    const uint4* Wb = (MODE == 1) ? &g_W1[nb][0][0] : &g_W2[nb][0][0];

    float acc[2][8][4];
    #pragma unroll
    for (int a = 0; a < 2; a++)
        #pragma unroll
        for (int b = 0; b < 8; b++)
            #pragma unroll
            for (int q = 0; q < 4; q++) acc[a][b][q] = 0.f;

    // stage issue helper
    auto issue = [&](int kbi, int st){
        uint32_t base = sb + (uint32_t)st*STG;
        const uint4* wh = Wb + kbi*1024;
        #pragma unroll
        for (int i = 0; i < 4; i++)
            cpasync16(base + BH + (tid + 256*i)*16, wh + tid + 256*i);
        #pragma unroll
        for (int i = 0; i < 4; i++){
            int idx = tid + 256*i, row = idx >> 3, un = idx & 7;
            cpasync16(base + AH + SWZ(row*128 + un*16),
                      Abase + (size_t)(m0+row)*ROWB + kbi*128 + un*16);
        }
        asm volatile("cp.async.commit_group;");
    };

    // ---- prologue: stages 0..2 in flight ----
    issue(0, 0); issue(1, 1); issue(2, 2);
    asm volatile("cp.async.wait_group 2;" ::: "memory");
    __syncthreads();

    Frag fr[2];
    ldfrag(fr[0], sb + 0*STG, 0, wm, wn, lane, AH, BH);

    for (int kb = 0; kb < KIT; kb++){
        const uint32_t scur = sb + (uint32_t)(kb & 3)*STG;
        #pragma unroll
        for (int kk = 0; kk < 4; kk++){
            const int cur = kk & 1;
            if (kk == 3){
                asm volatile("cp.async.wait_group 1;" ::: "memory");
                __syncthreads();
                if (kb + 3 < KIT) issue(kb + 3, (kb + 3) & 3);
                ldfrag(fr[cur^1], sb + (uint32_t)((kb+1) & 3)*STG, 0, wm, wn, lane, AH, BH);
            } else {
                ldfrag(fr[cur^1], scur, kk + 1, wm, wn, lane, AH, BH);
            }
            mmastep(acc, fr[cur]);
        }
    }

    // ---- epilogue ----
    const int mrow = lane >> 2;
    const int ncol = (lane & 3) * 2;
    if (MODE == 1){
        #pragma unroll
        for (int mt = 0; mt < 2; mt++){
            #pragma unroll
            for (int nf = 0; nf < 8; nf++){
                int m    = m0 + wm*32 + mt*16 + mrow;
                int neff = nb*128 + wn*64 + nf*8 + ncol;
                int nc   = neff >> 1;
                g_xh[(size_t)m*N_ + nc]     = __floats2half2_rn(acc[mt][nf][0]*WINV, acc[mt][nf][1]*WINV);
                g_xh[(size_t)(m+8)*N_ + nc] = __floats2half2_rn(acc[mt][nf][2]*WINV, acc[mt][nf][3]*WINV);
            }
        }
        // fused chunk-end via precomputed lam-power table (WINV folded in)
        {
            int bidx = m0 >> 11;
            int c    = ((m0 + wm*32) >> 5) & (NCH_-1);
            #pragma unroll
            for (int nf = 0; nf < 8; nf++){
                int nc = nb*64 + wn*32 + nf*4 + (lane & 3);
                float2 w0 = g_pw[(mrow     )*512 + nc];
                float2 w1 = g_pw[(mrow +  8)*512 + nc];
                float2 w2 = g_pw[(mrow + 16)*512 + nc];
                float2 w3 = g_pw[(mrow + 24)*512 + nc];
                float er = w0.x*acc[0][nf][0] - w0.y*acc[0][nf][1]
                         + w1.x*acc[0][nf][2] - w1.y*acc[0][nf][3]
                         + w2.x*acc[1][nf][0] - w2.y*acc[1][nf][1]
                         + w3.x*acc[1][nf][2] - w3.y*acc[1][nf][3];
                float ei = w0.x*acc[0][nf][1] + w0.y*acc[0][nf][0]
                         + w1.x*acc[0][nf][3] + w1.y*acc[0][nf][2]
                         + w2.x*acc[1][nf][1] + w2.y*acc[1][nf][0]
                         + w3.x*acc[1][nf][3] + w3.y*acc[1][nf][2];
                #pragma unroll
                for (int s = 4; s <= 16; s <<= 1){
                    er += __shfl_xor_sync(0xFFFFFFFFu, er, s);
                    ei += __shfl_xor_sync(0xFFFFFFFFu, ei, s);
                }
                if (mrow == 0)
                    g_end[(bidx*NCH_ + c)*N_ + nc] = make_float2(er, ei);
            }
        }
    } else {
        #pragma unroll
        for (int mt = 0; mt < 2; mt++){
            #pragma unroll
            for (int nf = 0; nf < 8; nf++){
                int m = m0 + wm*32 + mt*16 + mrow;
                int n = nb*128 + wn*64 + nf*8 + ncol;
                float2 d = *(const float2*)&Dv[n];
                size_t i0 = (size_t)m*N_ + n;
                size_t i1 = (size_t)(m+8)*N_ + n;
                float2 u0 = __half22float2(*(const __half2*)&g_uh[i0]);
                float2 u1 = __half22float2(*(const __half2*)&g_uh[i1]);
                float2 y0 = make_float2(fmaf(d.x, u0.x, acc[mt][nf][0]*WINV),
                                        fmaf(d.y, u0.y, acc[mt][nf][1]*WINV));
                float2 y1 = make_float2(fmaf(d.x, u1.x, acc[mt][nf][2]*WINV),
                                        fmaf(d.y, u1.y, acc[mt][nf][3]*WINV));
                *(float2*)&yout[i0] = y0;
                *(float2*)&yout[i1] = y1;
            }
        }
    }
}

// ---------------------------------------------------------------------------
// Scan: carry (Horner over chunk ends) + full recurrence, write x. One pass.
// ---------------------------------------------------------------------------
__global__ __launch_bounds__(256) void scan_apply(const float* __restrict__ nu,
                                                  const float* __restrict__ theta)
{
    int gid = blockIdx.x * 256 + threadIdx.x;
    int n = gid & (N_-1);
    int c = (gid >> 9) & (NCH_-1);
    int b = gid >> 15;

    float en  = expf(nu[n]);
    float mag = expf(-en);
    float th  = theta[n];
    float lr  = mag * cosf(th);
    float li  = mag * sinf(th);

    float magL = expf(-(float)L_ * en);
    float aL   = (float)L_ * th;
    float lLr  = magL * cosf(aL);
    float lLi  = magL * sinf(aL);

    float cr = 0.f, ci = 0.f;
    for (int j = 0; j < c; j++){
        float2 e = g_end[(b*NCH_ + j)*N_ + n];
        float tr = cr*lLr - ci*lLi + e.x;
        float ti = cr*lLi + ci*lLr + e.y;
        cr = tr; ci = ti;
    }

    __half2* p = g_xh + ((size_t)(b*T_ + c*L_))*N_ + n;
    float xr = cr, xi = ci;
    for (int t0 = 0; t0 < L_; t0 += 16){
        __half2 v[16];
        #pragma unroll
        for (int j = 0; j < 16; j++) v[j] = p[(size_t)(t0+j)*N_];
        #pragma unroll
        for (int j = 0; j < 16; j++){
            float2 q = __half22float2(v[j]);
            float nr = fmaf(lr, xr, fmaf(-li, xi, q.x));
            float ni = fmaf(lr, xi, fmaf( li, xr, q.y));
            xr = nr; xi = ni;
            p[(size_t)(t0+j)*N_] = __floats2half2_rn(xr, xi);
        }
    }
}

// ---------------------------------------------------------------------------
extern "C" void kernel_launch(void* const* d_in, const int* in_sizes, int n_in,
                              void* d_out, int out_size)
{
    const float* u     = (const float*)d_in[0];
    const float* C_re  = (const float*)d_in[1];
    const float* C_im  = (const float*)d_in[2];
    const float* B_re  = (const float*)d_in[3];
    const float* B_im  = (const float*)d_in[4];
    const float* D     = (const float*)d_in[5];
    const float* nu    = (const float*)d_in[6];
    const float* theta = (const float*)d_in[7];
    const float* gamma = (const float*)d_in[8];
    float* y = (float*)d_out;

    const int SMEM = 131072;   // 4 stages x 32KB
    cudaFuncSetAttribute(gemm_tc<1>, cudaFuncAttributeMaxDynamicSharedMemorySize, SMEM);
    cudaFuncSetAttribute(gemm_tc<2>, cudaFuncAttributeMaxDynamicSharedMemorySize, SMEM);

    prep_all<<<4416, 256>>>(u, B_re, B_im, C_re, C_im, gamma, nu, theta);

    gemm_tc<1><<<dim3(8, M_/128), 256, SMEM>>>(D, (float*)0);

    scan_apply<<<1024, 256>>>(nu, theta);

    gemm_tc<2><<<dim3(4, M_/128), 256, SMEM>>>(D, y);
}

// round 14
// speedup vs baseline: 1.6125x; 1.6125x over previous
#include <cuda_runtime.h>
#include <cuda_fp16.h>
#include <cstdint>

#define B_   8
#define T_   2048
#define N_   512
#define M_   (B_*T_)      // 16384
#define L_   32           // scan chunk length == GEMM1 warp-tile m
#define NCH_ (T_/L_)      // 64

#define WSCALE 64.0f
#define WINV   (1.0f/64.0f)

typedef unsigned long long ull;

// Scratch
__device__ __half  g_uh[M_*N_];               // u as fp16
__device__ __half2 g_xh[M_*N_];               // x as fp16 complex (re=low, im=high)
__device__ float2  g_end[B_*NCH_*N_];
__device__ float2  g_pw[32*512];              // lam^{31-r} * WINV per (r, channel)
// Pre-transposed/swizzled fp16 weight tiles (scaled by WSCALE):
__device__ uint4 g_W1[8][8][1024];            // GEMM1 B'' (Neff=1024, K=512)
__device__ uint4 g_W2[4][16][1024];           // GEMM2 B'  (N=512, Keff=1024)

// ---------------------------------------------------------------------------
__device__ __forceinline__ uint32_t s2u(const void* p){
    uint32_t a;
    asm("{ .reg .u64 t; cvta.to.shared.u64 t, %1; cvt.u32.u64 %0, t; }" : "=r"(a) : "l"(p));
    return a;
}
#define SWZ(o) ((uint32_t)(o) ^ ((((uint32_t)(o))>>3)&0x70u))

__device__ __forceinline__ uint32_t cvt2h(float x0, float x1){
    uint32_t r;
    asm("cvt.rn.f16x2.f32 %0, %1, %2;" : "=r"(r) : "f"(x1), "f"(x0));
    return r;
}
__device__ __forceinline__ uint4 ldsm4(uint32_t addr){
    uint4 r;
    asm volatile("ldmatrix.sync.aligned.m8n8.x4.shared.b16 {%0,%1,%2,%3}, [%4];"
        : "=r"(r.x), "=r"(r.y), "=r"(r.z), "=r"(r.w) : "r"(addr));
    return r;
}
__device__ __forceinline__ void mma16816(float* c, uint4 a, uint32_t b0, uint32_t b1){
    asm volatile("mma.sync.aligned.m16n8k16.row.col.f32.f16.f16.f32 "
        "{%0,%1,%2,%3}, {%4,%5,%6,%7}, {%8,%9}, {%0,%1,%2,%3};"
        : "+f"(c[0]), "+f"(c[1]), "+f"(c[2]), "+f"(c[3])
        : "r"(a.x), "r"(a.y), "r"(a.z), "r"(a.w), "r"(b0), "r"(b1));
}
__device__ __forceinline__ void cpasync16(uint32_t dst, const void* src){
    asm volatile("cp.async.cg.shared.global [%0], [%1], 16;" :: "r"(dst), "l"(src));
}

// ---------------------------------------------------------------------------
// Merged prepass: [0,128) W1, [128,256) W2, [256,4352) u->fp16, [4352,4416) pw
// ---------------------------------------------------------------------------
__global__ __launch_bounds__(256) void prep_all(const float* __restrict__ u,
                                                const float* __restrict__ Bre,
                                                const float* __restrict__ Bim,
                                                const float* __restrict__ Cre,
                                                const float* __restrict__ Cim,
                                                const float* __restrict__ gamma,
                                                const float* __restrict__ nu,
                                                const float* __restrict__ theta)
{
    __shared__ float s0[64*36];
    __shared__ float s1[64*36];
    __shared__ float gs[64];
    int bid = blockIdx.x, tid = threadIdx.x;

    if (bid >= 4352){
        int item = (bid - 4352) * 256 + tid;     // 16384 items
        int r = item >> 9, nc = item & 511;
        int q = 31 - r;
        float en = expf(nu[nc]);
        float mg = expf(-(float)q * en) * WINV;
        float ang = (float)q * theta[nc];
        g_pw[r*512 + nc] = make_float2(mg * cosf(ang), mg * sinf(ang));
        return;
    }
    if (bid >= 256){
        int i = (bid - 256) * 256 + tid;
        const float4* p = (const float4*)(u) + (size_t)i*2;
        float4 a = p[0], b = p[1];
        uint4 H;
        H.x = cvt2h(a.x, a.y);
        H.y = cvt2h(a.z, a.w);
        H.z = cvt2h(b.x, b.y);
        H.w = cvt2h(b.z, b.w);
        ((uint4*)g_uh)[i] = H;
        return;
    }

    if (bid < 128){
        int kb = bid >> 4, nt = bid & 15;
        int n0 = nt*32, k0 = kb*64;
        #pragma unroll
        for (int i = 0; i < 2; i++){
            int idx = tid + 256*i;
            int row = idx >> 3, c4 = (idx & 7) * 4;
            *(float4*)&s0[row*36 + c4] = *(const float4*)&Bre[(size_t)(k0+row)*N_ + n0 + c4];
            *(float4*)&s1[row*36 + c4] = *(const float4*)&Bim[(size_t)(k0+row)*N_ + n0 + c4];
        }
        if (tid < 64) gs[tid] = gamma[k0 + tid];
        __syncthreads();
        #pragma unroll
        for (int i = 0; i < 2; i++){
            int uid = tid + 256*i;
            int jloc = uid >> 3, cl = uid & 7;
            int j = n0*2 + jloc;
            int nloc = jloc >> 1, p = jloc & 1;
            const float* sp = p ? s1 : s0;
            float vs[8];
            #pragma unroll
            for (int e = 0; e < 8; e++){
                int kl = cl*8 + e;
                vs[e] = sp[kl*36 + nloc] * gs[kl] * WSCALE;
            }
            uint4 H;
            H.x = cvt2h(vs[0], vs[1]);
            H.y = cvt2h(vs[2], vs[3]);
            H.z = cvt2h(vs[4], vs[5]);
            H.w = cvt2h(vs[6], vs[7]);
            int jl = j & 127;
            g_W1[j>>7][kb][jl*8 + (cl ^ (jl & 7))] = H;
        }
    } else {
        int b2 = bid - 128;
        int kb = b2 >> 3, jt = b2 & 7;
        int j0 = jt*64, k0 = kb*32;
        #pragma unroll
        for (int i = 0; i < 2; i++){
            int idx = tid + 256*i;
            int row = idx >> 4, c4 = (idx & 15) * 4;
            *(float4*)&s0[row*68 + c4] = *(const float4*)&Cre[(size_t)(k0+row)*N_ + j0 + c4];
            *(float4*)&s1[row*68 + c4] = *(const float4*)&Cim[(size_t)(k0+row)*N_ + j0 + c4];
        }
        __syncthreads();
        #pragma unroll
        for (int i = 0; i < 2; i++){
            int uid = tid + 256*i;
            int jloc = uid >> 3, cl = uid & 7;
            int j = j0 + jloc;
            float vs[8];
            #pragma unroll
            for (int e = 0; e < 8; e++){
                int kel = cl*8 + e;
                int kl = kel >> 1;
                float v = (kel & 1) ? -s1[kl*68 + jloc] : s0[kl*68 + jloc];
                vs[e] = v * WSCALE;
            }
            uint4 H;
            H.x = cvt2h(vs[0], vs[1]);
            H.y = cvt2h(vs[2], vs[3]);
            H.z = cvt2h(vs[4], vs[5]);
            H.w = cvt2h(vs[6], vs[7]);
            int jl = j & 127;
            g_W2[j>>7][kb][jl*8 + (cl ^ (jl & 7))] = H;
        }
    }
}

// ---------------------------------------------------------------------------
// HMMA GEMM (round-9 champion shape): fp16, pure cp.async A+B, double-buffered
// smem, 128x128 tile, 8 warps (4x2), warp 32x64, 2 CTAs/SM.
// MODE 1: g_xh = uh @ W1 (+ table-fused chunk ends). MODE 2: y = x @ W2 + D*u.
// ---------------------------------------------------------------------------
template<int MODE>
__global__ __launch_bounds__(256, 2) void gemm_tc(const float* __restrict__ Dv,
                                                  float* __restrict__ yout)
{
    constexpr int KIT = (MODE == 1) ? 8 : 16;
    constexpr int ROWB = (MODE == 1) ? 1024 : 2048;   // A row stride in bytes
    constexpr uint32_t STG = 32768;
    constexpr uint32_t AH = 0, BH = 16384;

    extern __shared__ char sm[];
    const uint32_t sb = s2u(sm);

    const int tid  = threadIdx.x;
    const int lane = tid & 31, warp = tid >> 5;
    const int wm = warp >> 1, wn = warp & 1;
    const int nb = blockIdx.x;              // n-block FAST -> A stripe reuse in L2
    const int m0 = blockIdx.y * 128;

    const char* Abase = (MODE == 1) ? (const char*)g_uh : (const char*)g_xh;
    const uint4* Wb = (MODE == 1) ? &g_W1[nb][0][0] : &g_W2[nb][0][0];

    float acc[2][8][4];
    #pragma unroll
    for (int a = 0; a < 2; a++)
        #pragma unroll
        for (int b = 0; b < 8; b++)
            #pragma unroll
            for (int q = 0; q < 4; q++) acc[a][b][q] = 0.f;

    // ---- prologue: stage 0 ----
    {
        #pragma unroll
        for (int i = 0; i < 4; i++)
            cpasync16(sb + BH + (tid + 256*i)*16, Wb + tid + 256*i);
        #pragma unroll
        for (int i = 0; i < 4; i++){
            int idx = tid + 256*i, row = idx >> 3, un = idx & 7;
            cpasync16(sb + AH + SWZ(row*128 + un*16),
                      Abase + (size_t)(m0+row)*ROWB + un*16);
        }
        asm volatile("cp.async.commit_group;");
    }

    for (int kb = 0; kb < KIT; kb++){
        const uint32_t sc = sb + (kb & 1)*STG;
        const uint32_t sn = sb + ((kb & 1) ^ 1)*STG;

        if (kb + 1 < KIT){
            const uint4* wh = Wb + (kb+1)*1024;
            #pragma unroll
            for (int i = 0; i < 4; i++)
                cpasync16(sn + BH + (tid + 256*i)*16, wh + tid + 256*i);
            #pragma unroll
            for (int i = 0; i < 4; i++){
                int idx = tid + 256*i, row = idx >> 3, un = idx & 7;
                cpasync16(sn + AH + SWZ(row*128 + un*16),
                          Abase + (size_t)(m0+row)*ROWB + (kb+1)*128 + un*16);
            }
            asm volatile("cp.async.commit_group;");
            asm volatile("cp.async.wait_group 1;" ::: "memory");
        } else {
            asm volatile("cp.async.wait_group 0;" ::: "memory");
        }
        __syncthreads();

        #pragma unroll
        for (int kk = 0; kk < 4; kk++){
            uint4 ah[2];
            #pragma unroll
            for (int mt = 0; mt < 2; mt++){
                uint32_t off = SWZ((wm*32 + mt*16 + (lane&15))*128 + (kk*2 + (lane>>4))*16);
                ah[mt] = ldsm4(sc + AH + off);
            }
            #pragma unroll
            for (int bt = 0; bt < 4; bt++){
                uint32_t off = SWZ((wn*64 + bt*16 + (lane&7) + ((lane>>4)<<3))*128
                                   + (kk*2 + ((lane>>3)&1))*16);
                uint4 bh = ldsm4(sc + BH + off);
                #pragma unroll
                for (int mt = 0; mt < 2; mt++){
                    mma16816(acc[mt][2*bt],   ah[mt], bh.x, bh.y);
                    mma16816(acc[mt][2*bt+1], ah[mt], bh.z, bh.w);
                }
            }
        }
        __syncthreads();
    }

    // Epilogue (undo WSCALE)
    const int mrow = lane >> 2;
    const int ncol = (lane & 3) * 2;
    if (MODE == 1){
        #pragma unroll
        for (int mt = 0; mt < 2; mt++){
            #pragma unroll
            for (int nf = 0; nf < 8; nf++){
                int m    = m0 + wm*32 + mt*16 + mrow;
                int neff = nb*128 + wn*64 + nf*8 + ncol;
                int nc   = neff >> 1;
                g_xh[(size_t)m*N_ + nc]     = __floats2half2_rn(acc[mt][nf][0]*WINV, acc[mt][nf][1]*WINV);
                g_xh[(size_t)(m+8)*N_ + nc] = __floats2half2_rn(acc[mt][nf][2]*WINV, acc[mt][nf][3]*WINV);
            }
        }
        // fused chunk-end via precomputed lam-power table (WINV folded in).
        // This warp's 32 rows == one scan chunk; acc rows: mrow, +8, +16, +24.
        {
            int bidx = m0 >> 11;
            int c    = ((m0 + wm*32) >> 5) & (NCH_-1);
            #pragma unroll
            for (int nf = 0; nf < 8; nf++){
                int nc = nb*64 + wn*32 + nf*4 + (lane & 3);
                float2 w0 = g_pw[(mrow     )*512 + nc];
                float2 w1 = g_pw[(mrow +  8)*512 + nc];
                float2 w2 = g_pw[(mrow + 16)*512 + nc];
                float2 w3 = g_pw[(mrow + 24)*512 + nc];
                float er = w0.x*acc[0][nf][0] - w0.y*acc[0][nf][1]
                         + w1.x*acc[0][nf][2] - w1.y*acc[0][nf][3]
                         + w2.x*acc[1][nf][0] - w2.y*acc[1][nf][1]
                         + w3.x*acc[1][nf][2] - w3.y*acc[1][nf][3];
                float ei = w0.x*acc[0][nf][1] + w0.y*acc[0][nf][0]
                         + w1.x*acc[0][nf][3] + w1.y*acc[0][nf][2]
                         + w2.x*acc[1][nf][1] + w2.y*acc[1][nf][0]
                         + w3.x*acc[1][nf][3] + w3.y*acc[1][nf][2];
                #pragma unroll
                for (int s = 4; s <= 16; s <<= 1){
                    er += __shfl_xor_sync(0xFFFFFFFFu, er, s);
                    ei += __shfl_xor_sync(0xFFFFFFFFu, ei, s);
                }
                if (mrow == 0)
                    g_end[(bidx*NCH_ + c)*N_ + nc] = make_float2(er, ei);
            }
        }
    } else {
        #pragma unroll
        for (int mt = 0; mt < 2; mt++){
            #pragma unroll
            for (int nf = 0; nf < 8; nf++){
                int m = m0 + wm*32 + mt*16 + mrow;
                int n = nb*128 + wn*64 + nf*8 + ncol;
                float2 d = *(const float2*)&Dv[n];
                size_t i0 = (size_t)m*N_ + n;
                size_t i1 = (size_t)(m+8)*N_ + n;
                float2 u0 = __half22float2(*(const __half2*)&g_uh[i0]);
                float2 u1 = __half22float2(*(const __half2*)&g_uh[i1]);
                float2 y0 = make_float2(fmaf(d.x, u0.x, acc[mt][nf][0]*WINV),
                                        fmaf(d.y, u0.y, acc[mt][nf][1]*WINV));
                float2 y1 = make_float2(fmaf(d.x, u1.x, acc[mt][nf][2]*WINV),
                                        fmaf(d.y, u1.y, acc[mt][nf][3]*WINV));
                *(float2*)&yout[i0] = y0;
                *(float2*)&yout[i1] = y1;
            }
        }
    }
}

// ---------------------------------------------------------------------------
// Scan: carry (Horner over chunk ends) + full recurrence, write x. One pass.
// ---------------------------------------------------------------------------
__global__ __launch_bounds__(256) void scan_apply(const float* __restrict__ nu,
                                                  const float* __restrict__ theta)
{
    int gid = blockIdx.x * 256 + threadIdx.x;
    int n = gid & (N_-1);
    int c = (gid >> 9) & (NCH_-1);
    int b = gid >> 15;

    float en  = expf(nu[n]);
    float mag = expf(-en);
    float th  = theta[n];
    float lr  = mag * cosf(th);
    float li  = mag * sinf(th);

    float magL = expf(-(float)L_ * en);
    float aL   = (float)L_ * th;
    float lLr  = magL * cosf(aL);
    float lLi  = magL * sinf(aL);

    float cr = 0.f, ci = 0.f;
    for (int j = 0; j < c; j++){
        float2 e = g_end[(b*NCH_ + j)*N_ + n];
        float tr = cr*lLr - ci*lLi + e.x;
        float ti = cr*lLi + ci*lLr + e.y;
        cr = tr; ci = ti;
    }

    __half2* p = g_xh + ((size_t)(b*T_ + c*L_))*N_ + n;
    float xr = cr, xi = ci;
    for (int t0 = 0; t0 < L_; t0 += 16){
        __half2 v[16];
        #pragma unroll
        for (int j = 0; j < 16; j++) v[j] = p[(size_t)(t0+j)*N_];
        #pragma unroll
        for (int j = 0; j < 16; j++){
            float2 q = __half22float2(v[j]);
            float nr = fmaf(lr, xr, fmaf(-li, xi, q.x));
            float ni = fmaf(lr, xi, fmaf( li, xr, q.y));
            xr = nr; xi = ni;
            p[(size_t)(t0+j)*N_] = __floats2half2_rn(xr, xi);
        }
    }
}

// ---------------------------------------------------------------------------
extern "C" void kernel_launch(void* const* d_in, const int* in_sizes, int n_in,
                              void* d_out, int out_size)
{
    const float* u     = (const float*)d_in[0];
    const float* C_re  = (const float*)d_in[1];
    const float* C_im  = (const float*)d_in[2];
    const float* B_re  = (const float*)d_in[3];
    const float* B_im  = (const float*)d_in[4];
    const float* D     = (const float*)d_in[5];
    const float* nu    = (const float*)d_in[6];
    const float* theta = (const float*)d_in[7];
    const float* gamma = (const float*)d_in[8];
    float* y = (float*)d_out;

    const int SMEM = 65536;
    cudaFuncSetAttribute(gemm_tc<1>, cudaFuncAttributeMaxDynamicSharedMemorySize, SMEM);
    cudaFuncSetAttribute(gemm_tc<2>, cudaFuncAttributeMaxDynamicSharedMemorySize, SMEM);

    prep_all<<<4416, 256>>>(u, B_re, B_im, C_re, C_im, gamma, nu, theta);

    gemm_tc<1><<<dim3(8, M_/128), 256, SMEM>>>(D, (float*)0);

    scan_apply<<<1024, 256>>>(nu, theta);

    gemm_tc<2><<<dim3(4, M_/128), 256, SMEM>>>(D, y);
}